// round 4
// baseline (speedup 1.0000x reference)
#include <cuda_runtime.h>
#include <cstdint>

#define BATCH 16384
#define DIM   1024
#define TT    128
#define BM    128                   // batch rows per CTA
#define NCTA  (BATCH/BM)            // 128
#define KC    32                    // K per chunk
#define NCHUNK (DIM/KC)             // 32
#define NSTAGE 3
#define ROWB  160                   // padded row stride (bytes): 32 floats + 32B pad
#define TILE_BYTES (128*ROWB)       // 20480
#define STAGE_BYTES (2*TILE_BYTES)  // 40960 (A + B)
#define MISC_OFF (NSTAGE*STAGE_BYTES)   // 122880
#define SMEM_DYN (MISC_OFF + 1024)
#define LSTR 130                    // logits row stride (floats)

__device__ float g_partials[NCTA];
__device__ unsigned int g_done = 0;   // self-resets via atomicInc wrap

// ---------------- PTX helpers ----------------
__device__ __forceinline__ uint32_t smem_u32(const void* p) {
    uint32_t a;
    asm("{ .reg .u64 t; cvta.to.shared.u64 t, %1; cvt.u32.u64 %0, t; }"
        : "=r"(a) : "l"(p));
    return a;
}
__device__ __forceinline__ void cp_async8(uint32_t saddr, const void* gaddr) {
    asm volatile("cp.async.ca.shared.global [%0], [%1], 8;"
                 :: "r"(saddr), "l"(gaddr) : "memory");
}
template <int IMM>
__device__ __forceinline__ uint2 lds64(uint32_t base) {
    uint2 v;
    asm volatile("ld.shared.v2.b32 {%0,%1}, [%2+%3];"
                 : "=r"(v.x), "=r"(v.y) : "r"(base), "n"(IMM));
    return v;
}
// raw f32 bits as tf32 operands: HW truncates low mantissa bits
__device__ __forceinline__ void mma_tf32(float d[4],
                                         uint32_t a0, uint32_t a1, uint32_t a2, uint32_t a3,
                                         uint32_t b0, uint32_t b1) {
    asm volatile(
        "mma.sync.aligned.m16n8k8.row.col.f32.tf32.tf32.f32 "
        "{%0,%1,%2,%3}, {%4,%5,%6,%7}, {%8,%9}, {%0,%1,%2,%3};"
        : "+f"(d[0]), "+f"(d[1]), "+f"(d[2]), "+f"(d[3])
        : "r"(a0), "r"(a1), "r"(a2), "r"(a3), "r"(b0), "r"(b1));
}

// ---------------- fused kernel ----------------
__global__ __launch_bounds__(256, 1)
void qrl_mma_kernel(const float* __restrict__ X,     // [B, D]
                    const float* __restrict__ W,     // [T, D]
                    const float* __restrict__ bias,  // [T]
                    const int*   __restrict__ di,    // [B, 12]
                    const int*   __restrict__ dm,    // [B, 12]
                    float* __restrict__ out)
{
    extern __shared__ __align__(128) char smem[];
    float* ls    = (float*)smem;                     // aliases stage buffers post-GEMM
    float* sbias = (float*)(smem + MISC_OFF);        // 128 floats
    float* sred  = (float*)(smem + MISC_OFF + 512);  // 8 floats
    int*   sflag = (int*)  (smem + MISC_OFF + 576);

    const uint32_t sbase = smem_u32(smem);
    const int tid  = threadIdx.x;
    const int wid  = tid >> 5;
    const int lane = tid & 31;
    const int bid  = blockIdx.x;
    const int row0 = bid * BM;

    const int wm = wid & 3;        // 4 warps in M: 32 rows each
    const int wn = wid >> 2;       // 2 warps in N: 64 cols each
    const int g  = lane >> 2;      // 0..7
    const int c  = lane & 3;       // 0..3
    // fragment base offsets (row g of warp tile, k-pair c) — all further offsets are immediates
    const uint32_t aoff = (uint32_t)((wm * 32 + g) * ROWB + c * 8);
    const uint32_t boff = (uint32_t)(TILE_BYTES + (wn * 64 + g) * ROWB + c * 8);

    if (tid < TT) sbias[tid] = bias[tid];

    // ---- per-thread loader geometry: row = tid>>4 (+16 per i), seg = tid&15 (8B each) ----
    const int lrow = tid >> 4;
    const int lseg = tid & 15;
    const uint32_t ldst = (uint32_t)(lrow * ROWB + lseg * 8);

    auto load_chunk = [&](int kc, int st) {
        const uint32_t sa = sbase + st * STAGE_BYTES + ldst;
        const float* xg = X + (size_t)(row0 + lrow) * DIM + kc * KC + lseg * 2;
        const float* wg = W + (size_t)lrow * DIM + kc * KC + lseg * 2;
        #pragma unroll
        for (int i = 0; i < 8; ++i) {
            cp_async8(sa + i * (16 * ROWB),              xg + (size_t)i * 16 * DIM);
            cp_async8(sa + TILE_BYTES + i * (16 * ROWB), wg + (size_t)i * 16 * DIM);
        }
        asm volatile("cp.async.commit_group;" ::: "memory");
    };

    float acc[2][8][4];
    #pragma unroll
    for (int i = 0; i < 2; ++i)
        #pragma unroll
        for (int j = 0; j < 8; ++j)
            #pragma unroll
            for (int q = 0; q < 4; ++q) acc[i][j][q] = 0.f;

    load_chunk(0, 0);
    load_chunk(1, 1);

    for (int kc = 0; kc < NCHUNK; ++kc) {
        const int st = kc % NSTAGE;
        if (kc < NCHUNK - 2) asm volatile("cp.async.wait_group 1;" ::: "memory");
        else                 asm volatile("cp.async.wait_group 0;" ::: "memory");
        __syncthreads();
        if (kc + 2 < NCHUNK) load_chunk(kc + 2, (kc + 2) % NSTAGE);

        const uint32_t aA = sbase + st * STAGE_BYTES + aoff;
        const uint32_t aB = sbase + st * STAGE_BYTES + boff;

        // k-substep: LDS.64 pair = MMA positions (c, c+4); identical k-order for A & B
        #define KSTEP(KS) do {                                                     \
            uint2 A0 = lds64<(KS)*32 +    0>(aA);   /* rows g      (tile 0) */     \
            uint2 A1 = lds64<(KS)*32 + 1280>(aA);   /* rows g+8            */      \
            uint2 A2 = lds64<(KS)*32 + 2560>(aA);   /* rows g+16   (tile 1) */     \
            uint2 A3 = lds64<(KS)*32 + 3840>(aA);   /* rows g+24           */      \
            uint2 B0 = lds64<(KS)*32 + 0*1280>(aB);                                \
            uint2 B1 = lds64<(KS)*32 + 1*1280>(aB);                                \
            uint2 B2 = lds64<(KS)*32 + 2*1280>(aB);                                \
            uint2 B3 = lds64<(KS)*32 + 3*1280>(aB);                                \
            uint2 B4 = lds64<(KS)*32 + 4*1280>(aB);                                \
            uint2 B5 = lds64<(KS)*32 + 5*1280>(aB);                                \
            uint2 B6 = lds64<(KS)*32 + 6*1280>(aB);                                \
            uint2 B7 = lds64<(KS)*32 + 7*1280>(aB);                                \
            mma_tf32(acc[0][0], A0.x, A1.x, A0.y, A1.y, B0.x, B0.y);               \
            mma_tf32(acc[0][1], A0.x, A1.x, A0.y, A1.y, B1.x, B1.y);               \
            mma_tf32(acc[0][2], A0.x, A1.x, A0.y, A1.y, B2.x, B2.y);               \
            mma_tf32(acc[0][3], A0.x, A1.x, A0.y, A1.y, B3.x, B3.y);               \
            mma_tf32(acc[0][4], A0.x, A1.x, A0.y, A1.y, B4.x, B4.y);               \
            mma_tf32(acc[0][5], A0.x, A1.x, A0.y, A1.y, B5.x, B5.y);               \
            mma_tf32(acc[0][6], A0.x, A1.x, A0.y, A1.y, B6.x, B6.y);               \
            mma_tf32(acc[0][7], A0.x, A1.x, A0.y, A1.y, B7.x, B7.y);               \
            mma_tf32(acc[1][0], A2.x, A3.x, A2.y, A3.y, B0.x, B0.y);               \
            mma_tf32(acc[1][1], A2.x, A3.x, A2.y, A3.y, B1.x, B1.y);               \
            mma_tf32(acc[1][2], A2.x, A3.x, A2.y, A3.y, B2.x, B2.y);               \
            mma_tf32(acc[1][3], A2.x, A3.x, A2.y, A3.y, B3.x, B3.y);               \
            mma_tf32(acc[1][4], A2.x, A3.x, A2.y, A3.y, B4.x, B4.y);               \
            mma_tf32(acc[1][5], A2.x, A3.x, A2.y, A3.y, B5.x, B5.y);               \
            mma_tf32(acc[1][6], A2.x, A3.x, A2.y, A3.y, B6.x, B6.y);               \
            mma_tf32(acc[1][7], A2.x, A3.x, A2.y, A3.y, B7.x, B7.y);               \
        } while (0)

        KSTEP(0); KSTEP(1); KSTEP(2); KSTEP(3);
        #undef KSTEP
    }

    // ---- write logits to smem (alias stage buffers) ----
    __syncthreads();
    #pragma unroll
    for (int i = 0; i < 2; ++i) {
        const int r0 = wm * 32 + i * 16 + g;
        #pragma unroll
        for (int j = 0; j < 8; ++j) {
            const int c0 = wn * 64 + j * 8 + 2 * c;
            *(float2*)&ls[(size_t)r0 * LSTR + c0]       = make_float2(acc[i][j][0], acc[i][j][1]);
            *(float2*)&ls[(size_t)(r0 + 8) * LSTR + c0] = make_float2(acc[i][j][2], acc[i][j][3]);
        }
    }
    __syncthreads();

    // ---- softmax + gather: 2 lanes per row ----
    const int r = tid >> 1;
    const int h = tid & 1;
    const float* lr = &ls[(size_t)r * LSTR];

    float mx = -3.0e38f;
    #pragma unroll
    for (int i = 0; i < 64; ++i) {
        int cc = h + 2 * i;
        mx = fmaxf(mx, lr[cc] + sbias[cc]);
    }
    mx = fmaxf(mx, __shfl_xor_sync(0xffffffffu, mx, 1));

    float se = 0.f;
    #pragma unroll
    for (int i = 0; i < 64; ++i) {
        int cc = h + 2 * i;
        se += __expf(lr[cc] + sbias[cc] - mx);
    }
    se += __shfl_xor_sync(0xffffffffu, se, 1);

    float gg = 0.f;
    const int* dip = di + (size_t)(row0 + r) * 12;
    const int* dmp = dm + (size_t)(row0 + r) * 12;
    #pragma unroll
    for (int j = 0; j < 12; ++j) {
        if ((j & 1) == h) {
            int idx = dip[j];
            if (dmp[j]) gg += __expf(lr[idx] + sbias[idx] - mx);
        }
    }
    gg += __shfl_xor_sync(0xffffffffu, gg, 1);

    float part = (h == 0) ? (gg / se) : 0.f;

    // deterministic block reduce (8 warps)
    #pragma unroll
    for (int o = 16; o; o >>= 1) part += __shfl_down_sync(0xffffffffu, part, o);
    if (lane == 0) sred[wid] = part;
    __syncthreads();
    if (tid == 0) {
        float s = ((sred[0] + sred[1]) + (sred[2] + sred[3]))
                + ((sred[4] + sred[5]) + (sred[6] + sred[7]));
        g_partials[bid] = s;
        __threadfence();
        unsigned old = atomicInc(&g_done, NCTA - 1);   // wraps to 0: replay-safe
        sflag[0] = (old == NCTA - 1) ? 1 : 0;
    }
    __syncthreads();

    // ---- fused finalize: last CTA reduces all partials ----
    if (sflag[0]) {
        __threadfence();
        float v = (tid < NCTA) ? g_partials[tid] : 0.f;
        #pragma unroll
        for (int o = 16; o; o >>= 1) v += __shfl_down_sync(0xffffffffu, v, o);
        if (lane == 0) sred[wid] = v;
        __syncthreads();
        if (tid == 0) {
            float s = ((sred[0] + sred[1]) + (sred[2] + sred[3]))
                    + ((sred[4] + sred[5]) + (sred[6] + sred[7]));
            out[0] = s * (1.0f / 65536.f);   // / (B * V)
        }
    }
}

extern "C" void kernel_launch(void* const* d_in, const int* in_sizes, int n_in,
                              void* d_out, int out_size) {
    const float* X  = (const float*)d_in[0];
    const float* W  = (const float*)d_in[1];
    const float* b  = (const float*)d_in[2];
    const int*   di = (const int*)d_in[3];
    const int*   dm = (const int*)d_in[4];

    cudaFuncSetAttribute(qrl_mma_kernel,
                         cudaFuncAttributeMaxDynamicSharedMemorySize, SMEM_DYN);
    qrl_mma_kernel<<<NCTA, 256, SMEM_DYN>>>(X, W, b, di, dm, (float*)d_out);
}